// round 3
// baseline (speedup 1.0000x reference)
#include <cuda_runtime.h>

#define NPTS   16384
#define NPOINT 4096
#define BATCH  2
#define NSAMP  32
#define CIN    64

#define OUT_XYZ   0
#define OUT_FEAT  (BATCH*NPOINT*3)                 /* 24576 */
#define OUT_SAMP  (OUT_FEAT + BATCH*128*NPOINT)    /* 1073152 */

// scratch (module-static device memory — no runtime allocation)
__device__ float g_featsT[BATCH*NPTS*CIN];   // features transposed to [B,N,C]
__device__ int   g_idx[BATCH*NPOINT*NSAMP];  // ball query result

// ---------------------------------------------------------------------------
// K1: transpose features [B,C,N] -> g_featsT [B,N,C]
// ---------------------------------------------------------------------------
__global__ void k_transpose(const float* __restrict__ f) {
    __shared__ float tile[32][33];
    int b = blockIdx.z;
    int nBase = blockIdx.x * 32, cBase = blockIdx.y * 32;
    const float* src = f + (size_t)b * CIN * NPTS;
    float* dst = g_featsT + (size_t)b * NPTS * CIN;
    int tx = threadIdx.x, ty = threadIdx.y;  // 32 x 8
    #pragma unroll
    for (int i = 0; i < 32; i += 8)
        tile[ty + i][tx] = src[(size_t)(cBase + ty + i) * NPTS + nBase + tx];
    __syncthreads();
    #pragma unroll
    for (int i = 0; i < 32; i += 8)
        dst[(size_t)(nBase + ty + i) * CIN + cBase + tx] = tile[tx][ty + i];
}

// ---------------------------------------------------------------------------
// K2: ball query, warp per centroid. Ordered first-32 selection via ballot.
// Also writes new_xyz and samp_idx sections of the output.
// Distance uses the reference's expanded form with rn intrinsics (no FMA
// contraction) and the exact f32 threshold float(0.4*0.4).
// ---------------------------------------------------------------------------
__global__ void k_ballquery(const float* __restrict__ xyz, float* __restrict__ out) {
    const float R2C = (float)(0.4 * 0.4);  // matches jnp weak-typed cast
    int warp = (blockIdx.x * blockDim.x + threadIdx.x) >> 5;
    int lane = threadIdx.x & 31;
    if (warp >= BATCH * NPOINT) return;
    int b = warp / NPOINT, s = warp - b * NPOINT;
    const float* X = xyz + (size_t)b * NPTS * 3;
    float cx = X[s * 3 + 0], cy = X[s * 3 + 1], cz = X[s * 3 + 2];
    float cc = __fadd_rn(__fadd_rn(__fmul_rn(cx, cx), __fmul_rn(cy, cy)), __fmul_rn(cz, cz));

    int cnt = 0, first = 0;
    bool haveFirst = false;
    int* ibase = g_idx + (size_t)warp * NSAMP;

    for (int n0 = 0; n0 < NPTS && cnt < NSAMP; n0 += 32) {
        int n = n0 + lane;
        float px = X[n * 3 + 0], py = X[n * 3 + 1], pz = X[n * 3 + 2];
        float pp = __fadd_rn(__fadd_rn(__fmul_rn(px, px), __fmul_rn(py, py)), __fmul_rn(pz, pz));
        float dt = __fadd_rn(__fadd_rn(__fmul_rn(cx, px), __fmul_rn(cy, py)), __fmul_rn(cz, pz));
        float d2 = __fsub_rn(__fadd_rn(cc, pp), __fmul_rn(2.0f, dt));
        bool pred = d2 < R2C;
        unsigned m = __ballot_sync(0xffffffffu, pred);
        if (m) {
            if (!haveFirst) { first = n0 + __ffs(m) - 1; haveFirst = true; }
            if (pred) {
                int rank = cnt + __popc(m & ((1u << lane) - 1u));
                if (rank < NSAMP) ibase[rank] = n;
            }
            cnt += __popc(m);
            if (cnt > NSAMP) cnt = NSAMP;
        }
    }
    // fill empty slots with first hit (0 if none)
    if (lane >= cnt) ibase[lane] = first;

    // outputs: new_xyz [B,S,3] and samp_idx [B,S]
    if (lane == 0) {
        float* o = out + OUT_XYZ + (size_t)(b * NPOINT + s) * 3;
        o[0] = cx; o[1] = cy; o[2] = cz;
        out[OUT_SAMP + b * NPOINT + s] = (float)s;
    }
}

// ---------------------------------------------------------------------------
// K3: fused gather + 3-layer MLP + max-pool. 128 threads, 2 centroids (64 rows).
// ---------------------------------------------------------------------------
#define LDA 69
#define LDB 65
#define LDC 129
#define OFF_W1 0
#define OFF_B1 4288
#define OFF_W2 4352
#define OFF_B2 8448
#define OFF_W3 8512
#define OFF_B3 16704
#define OFF_A  16832   /* 64*69 = 4416 floats */
#define OFF_Bb 21248   /* 64*65 = 4160 floats */
#define SMEM_FLOATS 25408

__global__ void __launch_bounds__(128, 2) k_mlp(
    const float* __restrict__ xyz,
    const float* __restrict__ W1, const float* __restrict__ b1,
    const float* __restrict__ W2, const float* __restrict__ b2,
    const float* __restrict__ W3, const float* __restrict__ b3,
    float* __restrict__ out)
{
    extern __shared__ float sm[];
    const int tid = threadIdx.x;

    // load weights + biases into smem
    for (int i = tid; i < 4288; i += 128) sm[OFF_W1 + i] = W1[i];
    for (int i = tid; i < 4096; i += 128) sm[OFF_W2 + i] = W2[i];
    for (int i = tid; i < 8192; i += 128) sm[OFF_W3 + i] = W3[i];
    if (tid < 64)  { sm[OFF_B1 + tid] = b1[tid]; sm[OFF_B2 + tid] = b2[tid]; }
    sm[OFF_B3 + tid] = b3[tid];

    const int cta = blockIdx.x;         // 0..4095
    const int b = cta >> 11;            // / 2048
    const int s0 = (cta & 2047) * 2;    // 2 centroids per CTA
    const float* X = xyz + (size_t)b * NPTS * 3;
    const float* F = g_featsT + (size_t)b * NPTS * CIN;

    // gather: 64 rows x 67 cols into bufA. 2 threads per row.
    {
        int r = tid >> 1, half = tid & 1;    // r in 0..63
        int s = s0 + (r >> 5);
        int k = r & 31;
        int n = g_idx[((size_t)(b * NPOINT + s)) * NSAMP + k];
        float* arow = sm + OFF_A + r * LDA;
        if (half == 0) {
            arow[0] = X[n * 3 + 0] - X[s * 3 + 0];
            arow[1] = X[n * 3 + 1] - X[s * 3 + 1];
            arow[2] = X[n * 3 + 2] - X[s * 3 + 2];
            const float4* fr = (const float4*)(F + (size_t)n * CIN);
            #pragma unroll
            for (int q = 0; q < 8; q++) {
                float4 v = fr[q];
                arow[3 + 4 * q] = v.x; arow[4 + 4 * q] = v.y;
                arow[5 + 4 * q] = v.z; arow[6 + 4 * q] = v.w;
            }
        } else {
            const float4* fr = (const float4*)(F + (size_t)n * CIN + 32);
            #pragma unroll
            for (int q = 0; q < 8; q++) {
                float4 v = fr[q];
                arow[35 + 4 * q] = v.x; arow[36 + 4 * q] = v.y;
                arow[37 + 4 * q] = v.z; arow[38 + 4 * q] = v.w;
            }
        }
    }
    __syncthreads();

    const int tx = tid & 15, ty = tid >> 4;   // 16 cols-groups x 8 row-groups
    float* Abuf = sm + OFF_A;
    float* Bbuf = sm + OFF_Bb;

    // ---- layer 1: relu(A[64x67] @ W1[67x64] + b1) -> Bbuf ----
    {
        float acc[8][4];
        #pragma unroll
        for (int i = 0; i < 8; i++)
            #pragma unroll
            for (int j = 0; j < 4; j++) acc[i][j] = 0.f;
        const float* wp = sm + OFF_W1 + tx * 4;
        #pragma unroll 4
        for (int k = 0; k < 67; k++) {
            float4 w = *(const float4*)(wp + k * 64);
            #pragma unroll
            for (int i = 0; i < 8; i++) {
                float a = Abuf[(ty + 8 * i) * LDA + k];
                acc[i][0] += a * w.x; acc[i][1] += a * w.y;
                acc[i][2] += a * w.z; acc[i][3] += a * w.w;
            }
        }
        float4 bb = *(const float4*)(sm + OFF_B1 + tx * 4);
        #pragma unroll
        for (int i = 0; i < 8; i++) {
            float* o = Bbuf + (ty + 8 * i) * LDB + tx * 4;
            o[0] = fmaxf(acc[i][0] + bb.x, 0.f);
            o[1] = fmaxf(acc[i][1] + bb.y, 0.f);
            o[2] = fmaxf(acc[i][2] + bb.z, 0.f);
            o[3] = fmaxf(acc[i][3] + bb.w, 0.f);
        }
    }
    __syncthreads();

    // ---- layer 2: relu(Bbuf[64x64] @ W2[64x64] + b2) -> Abuf ----
    {
        float acc[8][4];
        #pragma unroll
        for (int i = 0; i < 8; i++)
            #pragma unroll
            for (int j = 0; j < 4; j++) acc[i][j] = 0.f;
        const float* wp = sm + OFF_W2 + tx * 4;
        #pragma unroll 4
        for (int k = 0; k < 64; k++) {
            float4 w = *(const float4*)(wp + k * 64);
            #pragma unroll
            for (int i = 0; i < 8; i++) {
                float a = Bbuf[(ty + 8 * i) * LDB + k];
                acc[i][0] += a * w.x; acc[i][1] += a * w.y;
                acc[i][2] += a * w.z; acc[i][3] += a * w.w;
            }
        }
        float4 bb = *(const float4*)(sm + OFF_B2 + tx * 4);
        #pragma unroll
        for (int i = 0; i < 8; i++) {
            float* o = Abuf + (ty + 8 * i) * LDA + tx * 4;
            o[0] = fmaxf(acc[i][0] + bb.x, 0.f);
            o[1] = fmaxf(acc[i][1] + bb.y, 0.f);
            o[2] = fmaxf(acc[i][2] + bb.z, 0.f);
            o[3] = fmaxf(acc[i][3] + bb.w, 0.f);
        }
    }
    __syncthreads();

    // ---- layer 3: relu(Abuf[64x64] @ W3[64x128] + b3) -> regs -> smem (stride LDC) ----
    float acc3[8][8];
    #pragma unroll
    for (int i = 0; i < 8; i++)
        #pragma unroll
        for (int j = 0; j < 8; j++) acc3[i][j] = 0.f;
    {
        const float* wp = sm + OFF_W3 + tx * 8;
        #pragma unroll 4
        for (int k = 0; k < 64; k++) {
            float4 w0 = *(const float4*)(wp + k * 128);
            float4 w1 = *(const float4*)(wp + k * 128 + 4);
            #pragma unroll
            for (int i = 0; i < 8; i++) {
                float a = Abuf[(ty + 8 * i) * LDA + k];
                acc3[i][0] += a * w0.x; acc3[i][1] += a * w0.y;
                acc3[i][2] += a * w0.z; acc3[i][3] += a * w0.w;
                acc3[i][4] += a * w1.x; acc3[i][5] += a * w1.y;
                acc3[i][6] += a * w1.z; acc3[i][7] += a * w1.w;
            }
        }
    }
    __syncthreads();  // everyone done reading Abuf before overwriting region with H3

    {
        float4 bb0 = *(const float4*)(sm + OFF_B3 + tx * 8);
        float4 bb1 = *(const float4*)(sm + OFF_B3 + tx * 8 + 4);
        #pragma unroll
        for (int i = 0; i < 8; i++) {
            float* o = sm + OFF_A + (ty + 8 * i) * LDC + tx * 8;
            o[0] = fmaxf(acc3[i][0] + bb0.x, 0.f);
            o[1] = fmaxf(acc3[i][1] + bb0.y, 0.f);
            o[2] = fmaxf(acc3[i][2] + bb0.z, 0.f);
            o[3] = fmaxf(acc3[i][3] + bb0.w, 0.f);
            o[4] = fmaxf(acc3[i][4] + bb1.x, 0.f);
            o[5] = fmaxf(acc3[i][5] + bb1.y, 0.f);
            o[6] = fmaxf(acc3[i][6] + bb1.z, 0.f);
            o[7] = fmaxf(acc3[i][7] + bb1.w, 0.f);
        }
    }
    __syncthreads();

    // ---- max over 32 samples per centroid; write out[b][c][s] ----
    #pragma unroll
    for (int p = tid; p < 256; p += 128) {
        int g = p >> 7, c = p & 127;
        const float* h = sm + OFF_A + (g * 32) * LDC + c;
        float mx = h[0];
        #pragma unroll
        for (int kk = 1; kk < 32; kk++) mx = fmaxf(mx, h[kk * LDC]);
        out[OUT_FEAT + ((size_t)(b * 128 + c)) * NPOINT + (s0 + g)] = mx;
    }
}

// ---------------------------------------------------------------------------
extern "C" void kernel_launch(void* const* d_in, const int* in_sizes, int n_in,
                              void* d_out, int out_size) {
    const float* xyz      = (const float*)d_in[0];
    const float* features = (const float*)d_in[1];
    const float* W1 = (const float*)d_in[2];
    const float* b1 = (const float*)d_in[3];
    const float* W2 = (const float*)d_in[4];
    const float* b2 = (const float*)d_in[5];
    const float* W3 = (const float*)d_in[6];
    const float* b3 = (const float*)d_in[7];
    float* out = (float*)d_out;
    (void)in_sizes; (void)n_in; (void)out_size;

    cudaFuncSetAttribute(k_mlp, cudaFuncAttributeMaxDynamicSharedMemorySize,
                         SMEM_FLOATS * (int)sizeof(float));

    k_transpose<<<dim3(NPTS / 32, CIN / 32, BATCH), dim3(32, 8)>>>(features);
    k_ballquery<<<(BATCH * NPOINT * 32) / 256, 256>>>(xyz, out);
    k_mlp<<<BATCH * NPOINT / 2, 128, SMEM_FLOATS * sizeof(float)>>>(
        xyz, W1, b1, W2, b2, W3, b3, out);
}